// round 13
// baseline (speedup 1.0000x reference)
#include <cuda_runtime.h>
#include <cuda_fp16.h>
#include <cstdint>

#define T_TOK 8192
#define HDIM  1024
#define NEXP  8
#define TPAD  (T_TOK + NEXP*128)

#define BM 128
#define BN 128
#define BK 64
#define NITER 16        // 1024 / 64
#define NSTAGE 3
#define NCTA  296       // 2 x 148: fully co-resident persistent grid

#define NWUNIT 1024     // W-convert units
#define NRUNIT 1024     // router units
#define NUNIT  (NWUNIT + NRUNIT)

// ---------------- device scratch ----------------
__device__ int   g_counts[NEXP];
__device__ int   g_currel[NEXP];     // relative cursors for assign
__device__ int   g_expert[T_TOK];
__device__ float g_gate[T_TOK];
__device__ int   g_tokpad[TPAD];
__device__ int   g_bar1, g_bar2, g_fin;
__device__ __half g_xh[(size_t)T_TOK * HDIM];               // token order
__device__ __half g_wh[(size_t)NEXP * HDIM * HDIM];         // [e][n][k]

// ---------------- helpers ----------------
__device__ __forceinline__ uint32_t smem_u32(const void* p) {
    uint32_t a;
    asm("{ .reg .u64 t; cvta.to.shared.u64 t, %1; cvt.u32.u64 %0, t; }" : "=r"(a) : "l"(p));
    return a;
}
__device__ __forceinline__ void cp16(uint32_t dst, const void* src) {
    asm volatile("cp.async.cg.shared.global [%0], [%1], 16;" :: "r"(dst), "l"(src));
}
__device__ __forceinline__ void cp_commit() {
    asm volatile("cp.async.commit_group;" ::: "memory");
}
template <int N>
__device__ __forceinline__ void cp_wait() {
    asm volatile("cp.async.wait_group %0;" :: "n"(N) : "memory");
}
#define LDSM4(R, addr) \
    asm volatile("ldmatrix.sync.aligned.m8n8.x4.shared.b16 {%0,%1,%2,%3}, [%4];" \
                 : "=r"((R)[0]), "=r"((R)[1]), "=r"((R)[2]), "=r"((R)[3]) : "r"(addr))
#define MMA16816(D, A, B0, B1) \
    asm volatile("mma.sync.aligned.m16n8k16.row.col.f32.f16.f16.f32 " \
                 "{%0,%1,%2,%3}, {%4,%5,%6,%7}, {%8,%9}, {%0,%1,%2,%3};" \
                 : "+f"((D)[0]), "+f"((D)[1]), "+f"((D)[2]), "+f"((D)[3]) \
                 : "r"((A)[0]), "r"((A)[1]), "r"((A)[2]), "r"((A)[3]), "r"(B0), "r"(B1))

// grid barrier: safe because all NCTA CTAs are co-resident
__device__ __forceinline__ void grid_barrier(int* cnt) {
    __syncthreads();
    if (threadIdx.x == 0) {
        __threadfence();
        atomicAdd(cnt, 1);
        while (atomicAdd(cnt, 0) < NCTA) __nanosleep(32);
    }
    __syncthreads();
}

// SMEM layout (dynamic): A 3x16KB @0, B 3x16KB @49152, tok @98304, gate @98816,
// meta (off[9], cnt[8]) @99328. Phase A reuses [0..33KB) for rws/tile.
static constexpr uint32_t OFF_B    = 49152;
static constexpr uint32_t OFF_TOK  = 98304;
static constexpr uint32_t OFF_GATE = 98816;
static constexpr uint32_t OFF_META = 99328;
static constexpr uint32_t SMEM_TOTAL = 99456;

__device__ __forceinline__ void issue_stage(int j, int tid, const int* sTok, int n0,
                                            size_t ebase, uint32_t sbase) {
    int kin = j * BK;
    int buf = j % NSTAGE;
    const __half* Bb = g_wh + ebase;
    uint32_t as = sbase + (uint32_t)buf * 16384;
    uint32_t bs = sbase + OFF_B + (uint32_t)buf * 16384;
#pragma unroll
    for (int i = 0; i < 4; i++) {
        int op = tid + i * 256;
        int r = op >> 3, c = op & 7;
        cp16(as + r * 128 + ((c * 16) ^ ((r & 7) << 4)),
             g_xh + (size_t)sTok[r] * HDIM + kin + c * 8);
    }
#pragma unroll
    for (int i = 0; i < 4; i++) {
        int op = tid + i * 256;
        int r = op >> 3, c = op & 7;
        cp16(bs + r * 128 + ((c * 16) ^ ((r & 7) << 4)),
             Bb + (size_t)(n0 + r) * HDIM + kin + c * 8);
    }
    cp_commit();
}

__global__ __launch_bounds__(256, 2)
void fused_moe_kernel(const float* __restrict__ x,
                      const float* __restrict__ rw,
                      const float* __restrict__ rb,
                      const float* __restrict__ ew,
                      const float* __restrict__ eb,
                      float* __restrict__ out) {
    extern __shared__ __align__(1024) char smem[];
    const int tid = threadIdx.x;
    const int lane = tid & 31;
    const uint32_t sbase = smem_u32(smem);

    // ================= phase A: prep (W convert + router) =================
    float (*rws)[1028] = reinterpret_cast<float(*)[1028]>(smem);   // 32.9 KB
    float (*tile)[33]  = reinterpret_cast<float(*)[33]>(smem);     // 8.4 KB

    for (int w = blockIdx.x; w < NUNIT; w += NCTA) {
        if (w < NWUNIT) {
            // ---- W transpose + fp16 convert: 32n-strip x 256k-quadrant ----
            int n0 = (w & 31) * 32;
            int kq = (w >> 5) & 3;
            int e  = w >> 7;
            int tx = tid & 31, ty = tid >> 5;
            const float* W = ew + (size_t)e * HDIM * HDIM;
            int l  = tid & 31;
            int nr = tid >> 5;
            uint32_t* w32 = reinterpret_cast<uint32_t*>(g_wh);
            int kbeg = kq * 256, kend = kbeg + 256;
            for (int k0 = kbeg; k0 < kend; k0 += 64) {
#pragma unroll
                for (int p = 0; p < 8; p++)
                    tile[ty + p * 8][tx] = W[(size_t)(k0 + ty + p * 8) * HDIM + n0 + tx];
                __syncthreads();
#pragma unroll
                for (int q = 0; q < 4; q++) {
                    int n = nr + q * 8;
                    __half2 h = __floats2half2_rn(tile[2 * l][n], tile[2 * l + 1][n]);
                    size_t idx = ((size_t)e * HDIM + (n0 + n)) * (HDIM / 2) + (k0 / 2 + l);
                    w32[idx] = *reinterpret_cast<uint32_t*>(&h);
                }
                __syncthreads();
            }
        } else {
            // ---- router + x fp16 convert: 8 tokens per unit ----
#pragma unroll
            for (int i = 0; i < 32; i++) {
                int idx = tid + i * 256;
                rws[idx & 7][idx >> 3] = rw[idx];
            }
            __syncthreads();

            int gwarp = (w - NWUNIT) * 8 + (tid >> 5);
            const float* xr = x + (size_t)gwarp * HDIM;
            __half* hp = g_xh + (size_t)gwarp * HDIM;
            float acc[NEXP];
#pragma unroll
            for (int e = 0; e < NEXP; e++) acc[e] = 0.f;
#pragma unroll
            for (int i = 0; i < HDIM / 128; i++) {
                int h = (i * 32 + lane) * 4;
                float4 xv = *reinterpret_cast<const float4*>(xr + h);
                __half2 c0 = __floats2half2_rn(xv.x, xv.y);
                __half2 c1 = __floats2half2_rn(xv.z, xv.w);
                uint2 pk;
                pk.x = *reinterpret_cast<uint32_t*>(&c0);
                pk.y = *reinterpret_cast<uint32_t*>(&c1);
                *reinterpret_cast<uint2*>(hp + h) = pk;
#pragma unroll
                for (int e = 0; e < NEXP; e++) {
                    float4 wv = *reinterpret_cast<const float4*>(&rws[e][h]);
                    acc[e] += xv.x * wv.x + xv.y * wv.y + xv.z * wv.z + xv.w * wv.w;
                }
            }
#pragma unroll
            for (int e = 0; e < NEXP; e++) {
#pragma unroll
                for (int off = 16; off > 0; off >>= 1)
                    acc[e] += __shfl_xor_sync(0xffffffffu, acc[e], off);
            }
            if (lane == 0) {
                float logit[NEXP];
                float best = -1e30f;
                int   bi = 0;
#pragma unroll
                for (int e = 0; e < NEXP; e++) {
                    logit[e] = acc[e] + rb[e];
                    if (logit[e] > best) { best = logit[e]; bi = e; }
                }
                float s = 0.f;
#pragma unroll
                for (int e = 0; e < NEXP; e++) s += expf(logit[e] - best);
                g_expert[gwarp] = bi;
                g_gate[gwarp]   = 1.0f / s;
                atomicAdd(&g_counts[bi], 1);
            }
        }
        __syncthreads();
    }

    // ================= barrier 1: prep complete =================
    grid_barrier(&g_bar1);

    // offsets in smem meta region
    int* s_off = (int*)(smem + OFF_META);        // [9]
    int* s_cnt = (int*)(smem + OFF_META + 36);   // [8]
    if (tid == 0) {
        int o = 0;
#pragma unroll
        for (int e = 0; e < NEXP; e++) {
            int c = g_counts[e];
            s_cnt[e] = c;
            s_off[e] = o;
            o += ((c + 127) >> 7) << 7;
        }
        s_off[NEXP] = o;
    }
    __syncthreads();

    // ================= assign: token -> padded slot =================
    {
        int t = blockIdx.x * 256 + tid;
        if (t < T_TOK) {
            int e = g_expert[t];
            unsigned peers = __match_any_sync(__activemask(), e);
            int leader = __ffs(peers) - 1;
            int rank = __popc(peers & ((1u << lane) - 1));
            int base = 0;
            if (rank == 0) base = atomicAdd(&g_currel[e], __popc(peers));
            base = __shfl_sync(__activemask(), base, leader);
            g_tokpad[s_off[e] + base + rank] = t;
        }
    }

    // ================= barrier 2: dispatch complete =================
    grid_barrier(&g_bar2);

    // ================= GEMM: loop over tiles =================
    const int ntiles = (s_off[NEXP] >> 7) * (HDIM / BN);
    int* sTok = (int*)(smem + OFF_TOK);
    float* sGate = (float*)(smem + OFF_GATE);
    const int wid = tid >> 5;
    const int warp_m = (wid >> 1) * 32;
    const int warp_n = (wid & 1) * 64;
    const int idx = lane & 7, grp = lane >> 3;

    for (int tilei = blockIdx.x; tilei < ntiles; tilei += NCTA) {
        const int m0 = (tilei >> 3) * BM;
        const int n0 = (tilei & 7) * BN;
        int e = 0;
        while (m0 >= s_off[e + 1]) e++;
        const int rows_valid = min(BM, s_off[e] + s_cnt[e] - m0);
        const size_t ebase = (size_t)e * HDIM * HDIM;

        if (tid < 128) {
            int tok = g_tokpad[m0 + tid] & (T_TOK - 1);
            sTok[tid] = tok;
            sGate[tid] = g_gate[tok];
        }
        __syncthreads();

        issue_stage(0, tid, sTok, n0, ebase, sbase);
        issue_stage(1, tid, sTok, n0, ebase, sbase);
        issue_stage(2, tid, sTok, n0, ebase, sbase);

        const int arow = warp_m + (grp & 1) * 8 + idx;
        const uint32_t axor = (uint32_t)((arow & 7) << 4);
        const uint32_t acsel = (uint32_t)((grp >> 1) * 16);
        const int brow = warp_n + (grp >> 1) * 8 + idx;
        const uint32_t bxor = (uint32_t)((brow & 7) << 4);
        const uint32_t bcsel = (uint32_t)((grp & 1) * 16);

        float acc[2][8][4];
#pragma unroll
        for (int i = 0; i < 2; i++)
#pragma unroll
            for (int j = 0; j < 8; j++)
#pragma unroll
                for (int q = 0; q < 4; q++) acc[i][j][q] = 0.f;

        for (int k = 0; k < NITER; k++) {
            cp_wait<2>();
            __syncthreads();
            int buf = k % NSTAGE;
            uint32_t as = sbase + (uint32_t)buf * 16384;
            uint32_t bs = sbase + OFF_B + (uint32_t)buf * 16384;
#pragma unroll
            for (int step = 0; step < 4; step++) {
                uint32_t kc = (uint32_t)(step * 32);
                uint32_t a[2][4], b[4][4];
#pragma unroll
                for (int mt = 0; mt < 2; mt++)
                    LDSM4(a[mt], as + (uint32_t)(arow + mt * 16) * 128 + ((kc + acsel) ^ axor));
#pragma unroll
                for (int bt = 0; bt < 4; bt++)
                    LDSM4(b[bt], bs + (uint32_t)(brow + bt * 16) * 128 + ((kc + bcsel) ^ bxor));
#pragma unroll
                for (int mt = 0; mt < 2; mt++)
#pragma unroll
                    for (int bt = 0; bt < 4; bt++) {
                        MMA16816(acc[mt][2 * bt],     a[mt], b[bt][0], b[bt][1]);
                        MMA16816(acc[mt][2 * bt + 1], a[mt], b[bt][2], b[bt][3]);
                    }
            }
            __syncthreads();
            if (k + NSTAGE < NITER) issue_stage(k + NSTAGE, tid, sTok, n0, ebase, sbase);
            else cp_commit();
        }

        // epilogue
        const float* ebias = eb + (size_t)e * HDIM + n0;
        const int colq = (lane & 3) * 2;
#pragma unroll
        for (int mt = 0; mt < 2; mt++) {
            int r_lo = warp_m + mt * 16 + (lane >> 2);
            int r_hi = r_lo + 8;
            bool v_lo = r_lo < rows_valid, v_hi = r_hi < rows_valid;
            int   t_lo = sTok[r_lo],  t_hi = sTok[r_hi];
            float g_lo = sGate[r_lo], g_hi = sGate[r_hi];
            float* o_lo = out + (size_t)t_lo * HDIM + n0;
            float* o_hi = out + (size_t)t_hi * HDIM + n0;
#pragma unroll
            for (int nt = 0; nt < 8; nt++) {
                int col = warp_n + nt * 8 + colq;
                float2 bv = *reinterpret_cast<const float2*>(ebias + col);
                if (v_lo) {
                    float2 v;
                    v.x = g_lo * (acc[mt][nt][0] + bv.x);
                    v.y = g_lo * (acc[mt][nt][1] + bv.y);
                    *reinterpret_cast<float2*>(o_lo + col) = v;
                }
                if (v_hi) {
                    float2 v;
                    v.x = g_hi * (acc[mt][nt][2] + bv.x);
                    v.y = g_hi * (acc[mt][nt][3] + bv.y);
                    *reinterpret_cast<float2*>(o_hi + col) = v;
                }
            }
        }
        __syncthreads();   // protect sTok/sGate before next tile overwrites
    }
    cp_wait<0>();          // drain any trailing async groups before exit

    // ================= reset replay state (last CTA) =================
    __syncthreads();
    if (tid == 0) {
        __threadfence();
        if (atomicAdd(&g_fin, 1) == NCTA - 1) {
            g_bar1 = 0;
            g_bar2 = 0;
            g_fin  = 0;
#pragma unroll
            for (int e = 0; e < NEXP; e++) {
                g_counts[e] = 0;
                g_currel[e] = 0;
            }
            __threadfence();
        }
    }
}

// ---------------- launch ----------------
extern "C" void kernel_launch(void* const* d_in, const int* in_sizes, int n_in,
                              void* d_out, int out_size) {
    const float* x  = (const float*)d_in[0];
    const float* rw = (const float*)d_in[1];
    const float* rb = (const float*)d_in[2];
    const float* ew = (const float*)d_in[3];
    const float* eb = (const float*)d_in[4];
    float* out = (float*)d_out;

    cudaFuncSetAttribute(fused_moe_kernel,
                         cudaFuncAttributeMaxDynamicSharedMemorySize, SMEM_TOTAL);

    fused_moe_kernel<<<NCTA, 256, SMEM_TOTAL>>>(x, rw, rb, ew, eb, out);
}